// round 1
// baseline (speedup 1.0000x reference)
#include <cuda_runtime.h>
#include <math.h>

#define NB 4
#define NC 31
#define NH 128
#define NW 128
#define SLICE (NH*NW)          // 16384
#define VOL   (NB*NC*SLICE)    // 2031616
#define SMEM_FFT (SLICE * (int)sizeof(float2))  // 131072 bytes

// ---------------- scratch (static device allocations; no cudaMalloc) --------
__device__ float  g_Z[VOL];
__device__ float  g_X[VOL];
__device__ float  g_G1[VOL];
__device__ float  g_G21[VOL];
__device__ float  g_G22[VOL];
__device__ float  g_G23[VOL];
__device__ float  g_Uh[VOL];
__device__ float  g_Uv[VOL];
__device__ float  g_Us[VOL];
__device__ float  g_num[VOL];
__device__ float2 g_A[VOL];

// ---------------- helpers ---------------------------------------------------
__device__ __forceinline__ float shrinkf(float x, float t) {
    return copysignf(fmaxf(fabsf(x) - t, 0.0f), x);
}
__device__ __forceinline__ float2 cadd(float2 a, float2 b){ return make_float2(a.x+b.x, a.y+b.y); }
__device__ __forceinline__ float2 csub(float2 a, float2 b){ return make_float2(a.x-b.x, a.y-b.y); }

// ---------------- init: Z = X = Y, G* = 0 -----------------------------------
__global__ void k_init(const float* __restrict__ Y) {
    int i = blockIdx.x * blockDim.x + threadIdx.x;
    if (i >= VOL) return;
    float y = Y[i];
    g_Z[i] = y; g_X[i] = y;
    g_G1[i] = 0.f; g_G21[i] = 0.f; g_G22[i] = 0.f; g_G23[i] = 0.f;
}

// ---------------- stage 1: shrink (U) + numerator ---------------------------
// Uh = shrink(DhZ - G21/mu2, lam/mu2)  (DhZ = Z - roll(Z,-1,w))
// numer = mu1*X + G1 + mu2*( DhT(Uh+G21/mu2) + DvT(...) + DsT(...) )
// DhT(A)(p) = A(p) - A(p with w-1)
__global__ void k_stage1(float mu1, float mu2, float inv_mu2, float thr) {
    int i = blockIdx.x * blockDim.x + threadIdx.x;
    if (i >= VOL) return;
    int w = i & 127;
    int h = (i >> 7) & 127;
    int c = (i >> 14) % NC;

    int base_w = i - w;
    int base_h = i - (h << 7);
    int base_c = i - c * SLICE;

    int iw1 = base_w + ((w + 1) & 127);
    int iwm = base_w + ((w + 127) & 127);
    int ih1 = base_h + (((h + 1) & 127) << 7);
    int ihm = base_h + (((h + 127) & 127) << 7);
    int c1 = (c == NC-1) ? 0 : c + 1;
    int cm = (c == 0) ? NC-1 : c - 1;
    int ic1 = base_c + c1 * SLICE;
    int icm = base_c + cm * SLICE;

    float z   = g_Z[i];
    float zw1 = g_Z[iw1], zwm = g_Z[iwm];
    float zh1 = g_Z[ih1], zhm = g_Z[ihm];
    float zc1 = g_Z[ic1], zcm = g_Z[icm];

    float g21  = g_G21[i],  g22  = g_G22[i],  g23  = g_G23[i];
    float g21m = g_G21[iwm], g22m = g_G22[ihm], g23m = g_G23[icm];

    float uh = shrinkf((z - zw1) - g21 * inv_mu2, thr);
    float uv = shrinkf((z - zh1) - g22 * inv_mu2, thr);
    float us = shrinkf((z - zc1) - g23 * inv_mu2, thr);
    // neighbor U values (recomputed; identical formula at the neighbor point)
    float uhm = shrinkf((zwm - z) - g21m * inv_mu2, thr);
    float uvm = shrinkf((zhm - z) - g22m * inv_mu2, thr);
    float usm = shrinkf((zcm - z) - g23m * inv_mu2, thr);

    float Ah  = uh  + g21  * inv_mu2;
    float Ahm = uhm + g21m * inv_mu2;
    float Av  = uv  + g22  * inv_mu2;
    float Avm = uvm + g22m * inv_mu2;
    float As  = us  + g23  * inv_mu2;
    float Asm = usm + g23m * inv_mu2;

    float numer = mu1 * g_X[i] + g_G1[i]
                + mu2 * ((Ah - Ahm) + (Av - Avm) + (As - Asm));

    g_Uh[i] = uh; g_Uv[i] = uv; g_Us[i] = us;
    g_num[i] = numer;
}

// ---------------- forward 2D FFT per (n,c) slice (DIF; bit-rev output) ------
__global__ __launch_bounds__(1024) void k_fft2_fwd() {
    extern __shared__ float2 t[];
    int s = blockIdx.x, tid = threadIdx.x;
    const float* src = g_num + s * SLICE;
    for (int idx = tid; idx < SLICE; idx += 1024)
        t[idx] = make_float2(src[idx], 0.0f);
    __syncthreads();

    // rows (w axis), DIF, sign -
    #pragma unroll
    for (int hs = 6; hs >= 0; hs--) {
        int half = 1 << hs, len = half << 1;
        float fl = 2.0f / (float)len;
        for (int b = tid; b < 8192; b += 1024) {
            int r = b >> 6, j = b & 63;
            int grp = j >> hs, pos = j & (half - 1);
            int i0 = r * 128 + grp * len + pos, i1 = i0 + half;
            float2 a = t[i0], bb = t[i1];
            t[i0] = cadd(a, bb);
            float2 d = csub(a, bb);
            float sn, cs; sincospif(fl * (float)pos, &sn, &cs);
            t[i1] = make_float2(d.x * cs + d.y * sn, d.y * cs - d.x * sn); // d * (cs - i sn)
        }
        __syncthreads();
    }
    // cols (h axis), DIF, sign -
    #pragma unroll
    for (int hs = 6; hs >= 0; hs--) {
        int half = 1 << hs, len = half << 1;
        float fl = 2.0f / (float)len;
        for (int b = tid; b < 8192; b += 1024) {
            int w = b & 127, j = b >> 7;
            int grp = j >> hs, pos = j & (half - 1);
            int i0 = (grp * len + pos) * 128 + w, i1 = i0 + (half << 7);
            float2 a = t[i0], bb = t[i1];
            t[i0] = cadd(a, bb);
            float2 d = csub(a, bb);
            float sn, cs; sincospif(fl * (float)pos, &sn, &cs);
            t[i1] = make_float2(d.x * cs + d.y * sn, d.y * cs - d.x * sn);
        }
        __syncthreads();
    }
    float2* dst = g_A + s * SLICE;
    for (int idx = tid; idx < SLICE; idx += 1024) dst[idx] = t[idx];
}

// ---------------- C-axis: fwd 31-DFT, diagonal divide, inv 31-DFT -----------
__global__ __launch_bounds__(128) void k_cdft(float mu1, float mu2) {
    __shared__ float2 tw[NC];   // exp(-2*pi*i*m/31)
    __shared__ float  dc[NC];   // 2 - 2cos(2*pi*k/31)
    int tid = threadIdx.x;
    if (tid < NC) {
        float sn, cs; sincospif(2.0f * (float)tid / 31.0f, &sn, &cs);
        tw[tid] = make_float2(cs, -sn);
        dc[tid] = 2.0f - 2.0f * cs;
    }
    __syncthreads();

    int p = blockIdx.x * blockDim.x + tid;   // 0 .. NB*SLICE-1
    int w = p & 127, h = (p >> 7) & 127, n = p >> 14;
    // positions are bit-reversed frequencies from the DIF pass
    int hf = __brev((unsigned)h) >> 25;
    int wf = __brev((unsigned)w) >> 25;
    float ehw = (2.0f - 2.0f * cospif((float)hf * (2.0f / 128.0f)))
              + (2.0f - 2.0f * cospif((float)wf * (2.0f / 128.0f)));

    float2* base = g_A + (size_t)n * NC * SLICE + (h << 7) + w;

    float2 F[NC];
    #pragma unroll
    for (int k = 0; k < NC; k++) F[k] = make_float2(0.f, 0.f);

    for (int j = 0; j < NC; j++) {
        float2 x = base[j * SLICE];
        int m = 0;
        #pragma unroll
        for (int k = 0; k < NC; k++) {
            float2 tt = tw[m];
            F[k].x += x.x * tt.x - x.y * tt.y;
            F[k].y += x.x * tt.y + x.y * tt.x;
            m += j; if (m >= NC) m -= NC;
        }
    }
    #pragma unroll
    for (int k = 0; k < NC; k++) {
        float sc = 1.0f / (mu1 + mu2 * (dc[k] + ehw));
        F[k].x *= sc; F[k].y *= sc;
    }
    const float inv31 = 1.0f / 31.0f;
    for (int j = 0; j < NC; j++) {
        float2 acc = make_float2(0.f, 0.f);
        int m = 0;
        #pragma unroll
        for (int k = 0; k < NC; k++) {
            float2 tt = tw[m];  // use conj(tt)
            acc.x += F[k].x * tt.x + F[k].y * tt.y;
            acc.y += F[k].y * tt.x - F[k].x * tt.y;
            m += j; if (m >= NC) m -= NC;
        }
        base[j * SLICE] = make_float2(acc.x * inv31, acc.y * inv31);
    }
}

// ---------------- inverse 2D FFT per slice (DIT; bit-rev input) -------------
__global__ __launch_bounds__(1024) void k_fft2_inv(float* __restrict__ dstp) {
    extern __shared__ float2 t[];
    int s = blockIdx.x, tid = threadIdx.x;
    const float2* src = g_A + s * SLICE;
    for (int idx = tid; idx < SLICE; idx += 1024) t[idx] = src[idx];
    __syncthreads();

    // cols (h axis), DIT, sign +
    #pragma unroll
    for (int hs = 0; hs <= 6; hs++) {
        int half = 1 << hs, len = half << 1;
        float fl = 2.0f / (float)len;
        for (int b = tid; b < 8192; b += 1024) {
            int w = b & 127, j = b >> 7;
            int grp = j >> hs, pos = j & (half - 1);
            int i0 = (grp * len + pos) * 128 + w, i1 = i0 + (half << 7);
            float sn, cs; sincospif(fl * (float)pos, &sn, &cs);
            float2 x1 = t[i1];
            float2 tm = make_float2(x1.x * cs - x1.y * sn, x1.x * sn + x1.y * cs);
            float2 x0 = t[i0];
            t[i1] = csub(x0, tm);
            t[i0] = cadd(x0, tm);
        }
        __syncthreads();
    }
    // rows (w axis), DIT, sign +
    #pragma unroll
    for (int hs = 0; hs <= 6; hs++) {
        int half = 1 << hs, len = half << 1;
        float fl = 2.0f / (float)len;
        for (int b = tid; b < 8192; b += 1024) {
            int r = b >> 6, j = b & 63;
            int grp = j >> hs, pos = j & (half - 1);
            int i0 = r * 128 + grp * len + pos, i1 = i0 + half;
            float sn, cs; sincospif(fl * (float)pos, &sn, &cs);
            float2 x1 = t[i1];
            float2 tm = make_float2(x1.x * cs - x1.y * sn, x1.x * sn + x1.y * cs);
            float2 x0 = t[i0];
            t[i1] = csub(x0, tm);
            t[i0] = cadd(x0, tm);
        }
        __syncthreads();
    }
    float* dst = (dstp != nullptr) ? dstp : g_Z;
    dst += s * SLICE;
    const float scale = 1.0f / 16384.0f;
    for (int idx = tid; idx < SLICE; idx += 1024) dst[idx] = t[idx].x * scale;
}

// ---------------- stage 5: X / G updates ------------------------------------
__global__ void k_update(const float* __restrict__ Y, const float* __restrict__ inW,
                         float mu1, float mu2) {
    int i = blockIdx.x * blockDim.x + threadIdx.x;
    if (i >= VOL) return;
    int w = i & 127;
    int h = (i >> 7) & 127;
    int c = (i >> 14) % NC;
    int iw1 = (i - w) + ((w + 1) & 127);
    int ih1 = (i - (h << 7)) + (((h + 1) & 127) << 7);
    int c1 = (c == NC-1) ? 0 : c + 1;
    int ic1 = (i - c * SLICE) + c1 * SLICE;

    float z = g_Z[i];
    float zw1 = g_Z[iw1], zh1 = g_Z[ih1], zc1 = g_Z[ic1];
    float xw = inW[i], y = Y[i];
    float g1 = g_G1[i];
    float x = (xw * y + mu1 * z - g1) / (xw + mu1);
    g1 = g1 + mu1 * (x - z);
    g_X[i] = x; g_G1[i] = g1;
    g_G21[i] += mu2 * (g_Uh[i] - (z - zw1));
    g_G22[i] += mu2 * (g_Uv[i] - (z - zh1));
    g_G23[i] += mu2 * (g_Us[i] - (z - zc1));
}

// ---------------- launch ----------------------------------------------------
extern "C" void kernel_launch(void* const* d_in, const int* in_sizes, int n_in,
                              void* d_out, int out_size) {
    const float* Y   = (const float*)d_in[0];
    const float* inW = (const float*)d_in[1];
    float* out = (float*)d_out;

    cudaFuncSetAttribute(k_fft2_fwd, cudaFuncAttributeMaxDynamicSharedMemorySize, SMEM_FFT);
    cudaFuncSetAttribute(k_fft2_inv, cudaFuncAttributeMaxDynamicSharedMemorySize, SMEM_FFT);

    const int EB = (VOL + 255) / 256;

    k_init<<<EB, 256>>>(Y);

    double mu1d = 0.1, mu2d = 0.1;
    const double lam = 0.1;
    for (int it = 0; it < 20; it++) {
        float mu1 = (float)mu1d, mu2 = (float)mu2d;
        float inv_mu2 = (float)(1.0 / mu2d);
        float thr = (float)(lam / mu2d);

        k_stage1<<<EB, 256>>>(mu1, mu2, inv_mu2, thr);
        k_fft2_fwd<<<NB * NC, 1024, SMEM_FFT>>>();
        k_cdft<<<(NB * SLICE) / 128, 128>>>(mu1, mu2);
        k_fft2_inv<<<NB * NC, 1024, SMEM_FFT>>>(it == 19 ? out : nullptr);
        if (it < 19)
            k_update<<<EB, 256>>>(Y, inW, mu1, mu2);

        mu1d *= 1.05;
        mu2d *= 1.05;
    }
}

// round 2
// speedup vs baseline: 1.3205x; 1.3205x over previous
#include <cuda_runtime.h>
#include <math.h>

#define NB 4
#define NC 31
#define NK 16                 // Hermitian half of C-spectrum (k=0..15)
#define SLICE 16384           // 128*128
#define VOL   (NB*NC*SLICE)   // 2031616
#define PEN   (NB*SLICE)      // 65536 pencils
#define FVOL  (NB*NK*SLICE)   // 1048576 complex per spectral buffer

// ---------------- static scratch --------------------------------------------
__device__ float  g_Z[VOL];
__device__ float  g_X[VOL];
__device__ float  g_G1[VOL];
__device__ float  g_Ph[2][VOL];   // ping-pong: P = mu2*(U + G2/mu2) per direction
__device__ float  g_Pv[2][VOL];
__device__ float  g_Ps[VOL];      // c-direction: same-thread only, no ping-pong
__device__ float2 g_Fc[FVOL];
__device__ float2 g_Bb[FVOL];

__device__ __forceinline__ float shrinkf(float x, float t) {
    return copysignf(fmaxf(fabsf(x) - t, 0.0f), x);
}
__device__ __forceinline__ float2 cadd(float2 a, float2 b){ return make_float2(a.x+b.x, a.y+b.y); }
__device__ __forceinline__ float2 csub(float2 a, float2 b){ return make_float2(a.x-b.x, a.y-b.y); }

// ---------------- init ------------------------------------------------------
__global__ void k_init(const float* __restrict__ Y) {
    int i = blockIdx.x * blockDim.x + threadIdx.x;
    if (i >= VOL) return;
    float y = Y[i];
    g_Z[i] = y; g_X[i] = y;
    g_G1[i] = 0.f;
    g_Ph[0][i] = 0.f; g_Pv[0][i] = 0.f; g_Ps[i] = 0.f;
}

// ---------------- fused: G2-recover + shrink + numerator + real C-DFT -------
// Persisted state per direction: P_t = G2_t + mu2_t*U_t = mu2_t*A_t.
// Recovery:  G2_t = P_{t-1} - mu2_{t-1} * D(Z_current).
// Output: g_Fc[k] = sum_c numer_c * exp(-2*pi*i*k*c/31), k=0..15.
__global__ __launch_bounds__(256) void k_cfwd(int pp, float mu1, float mu2,
                                              float mu2p, float inv_mu2, float thr)
{
    __shared__ float2 tw[NC];  // exp(-2*pi*i*m/31)
    int tid = threadIdx.x;
    if (tid < NC) { float s, c; sincospif((float)tid * (2.f/31.f), &s, &c);
                    tw[tid] = make_float2(c, -s); }
    __syncthreads();

    int p  = blockIdx.x * 256 + tid;       // pencil id
    int n  = p >> 14, hw = p & 16383;
    int h  = hw >> 7, w = hw & 127;
    int ow1 = ((w + 1)   & 127) - w;
    int owm = ((w + 127) & 127) - w;
    int oh1 = ((((h + 1)   & 127) - h) << 7);
    int ohm = ((((h + 127) & 127) - h) << 7);
    int base = n * (NC * SLICE) + hw;

    const float* __restrict__ Ph_in  = g_Ph[pp];
    float*       __restrict__ Ph_out = g_Ph[pp ^ 1];
    const float* __restrict__ Pv_in  = g_Pv[pp];
    float*       __restrict__ Pv_out = g_Pv[pp ^ 1];

    float z0  = g_Z[base];
    float z30 = g_Z[base + 30 * SLICE];
    // A_s at c=30 (needed as "previous" for c=0); recomputed & stored at c=30.
    float As_prev;
    {
        float d  = z30 - z0;
        float g2 = g_Ps[base + 30 * SLICE] - mu2p * d;
        float q  = g2 * inv_mu2;
        As_prev  = shrinkf(d - q, thr) + q;
    }

    float2 F[NK];
    #pragma unroll
    for (int k = 0; k < NK; k++) F[k] = make_float2(0.f, 0.f);

    float zc = z0;
    for (int c = 0; c < NC; c++) {
        int i = base + c * SLICE;
        float znext = (c < 30) ? g_Z[i + SLICE] : z0;
        float zw1 = g_Z[i + ow1], zwm = g_Z[i + owm];
        float zh1 = g_Z[i + oh1], zhm = g_Z[i + ohm];

        // horizontal (w)
        float dh  = zc - zw1;
        float g2h = Ph_in[i] - mu2p * dh;
        float qh  = g2h * inv_mu2;
        float Ah  = shrinkf(dh - qh, thr) + qh;
        Ph_out[i] = mu2 * Ah;
        float dhm  = zwm - zc;
        float g2hm = Ph_in[i + owm] - mu2p * dhm;
        float qhm  = g2hm * inv_mu2;
        float Ahm  = shrinkf(dhm - qhm, thr) + qhm;

        // vertical (h)
        float dv  = zc - zh1;
        float g2v = Pv_in[i] - mu2p * dv;
        float qv  = g2v * inv_mu2;
        float Av  = shrinkf(dv - qv, thr) + qv;
        Pv_out[i] = mu2 * Av;
        float dvm  = zhm - zc;
        float g2vm = Pv_in[i + ohm] - mu2p * dvm;
        float qvm  = g2vm * inv_mu2;
        float Avm  = shrinkf(dvm - qvm, thr) + qvm;

        // spectral (c)
        float ds  = zc - znext;
        float g2s = g_Ps[i] - mu2p * ds;
        float qs  = g2s * inv_mu2;
        float As  = shrinkf(ds - qs, thr) + qs;
        g_Ps[i]   = mu2 * As;

        float numer = mu1 * g_X[i] + g_G1[i]
                    + mu2 * ((Ah - Ahm) + (Av - Avm) + (As - As_prev));
        As_prev = As;

        // accumulate real 31-point DFT (Hermitian half)
        F[0].x += numer;
        int m = 0;
        #pragma unroll
        for (int k = 1; k < NK; k++) {
            m += c; if (m >= NC) m -= NC;
            float2 t = tw[m];
            F[k].x = fmaf(numer, t.x, F[k].x);
            F[k].y = fmaf(numer, t.y, F[k].y);
        }
        zc = znext;
    }

    int fb = (n * NK) * SLICE + hw;
    #pragma unroll
    for (int k = 0; k < NK; k++) g_Fc[fb + k * SLICE] = F[k];
}

// ---------------- 2D FFT passes (split row/col, table twiddles) -------------
// fwd: DIF (natural->bitrev), sign -.  inv: DIT (bitrev->natural), sign +.
// twd[m] = (cos(2*pi*m/128), sin(2*pi*m/128)), index m = pos << (6-hs).

__global__ __launch_bounds__(256) void k_rows_fwd() {   // g_Fc -> g_Bb, w axis
    __shared__ float2 t[4096];
    __shared__ float2 twd[64];
    int tid = threadIdx.x;
    if (tid < 64) { float s, c; sincospif((float)tid * (2.f/128.f), &s, &c);
                    twd[tid] = make_float2(c, s); }
    int s  = blockIdx.x >> 2;
    int r0 = (blockIdx.x & 3) << 5;
    const float2* sp = g_Fc + s * SLICE + (r0 << 7);
    for (int idx = tid; idx < 4096; idx += 256) t[idx] = sp[idx];
    __syncthreads();
    #pragma unroll
    for (int hs = 6; hs >= 0; hs--) {
        int half = 1 << hs;
        for (int b = tid; b < 2048; b += 256) {
            int r = b >> 6, j = b & 63;
            int grp = j >> hs, pos = j & (half - 1);
            int i0 = (r << 7) + (grp << (hs + 1)) + pos, i1 = i0 + half;
            float2 a = t[i0], c = t[i1];
            t[i0] = cadd(a, c);
            float2 d = csub(a, c);
            float2 wv = twd[pos << (6 - hs)];
            t[i1] = make_float2(d.x * wv.x + d.y * wv.y, d.y * wv.x - d.x * wv.y);
        }
        __syncthreads();
    }
    float2* dp = g_Bb + s * SLICE + (r0 << 7);
    for (int idx = tid; idx < 4096; idx += 256) dp[idx] = t[idx];
}

__global__ __launch_bounds__(256) void k_cols_fwd() {   // g_Bb -> g_Fc, h axis
    __shared__ float2 t[4096];
    __shared__ float2 twd[64];
    int tid = threadIdx.x;
    if (tid < 64) { float s, c; sincospif((float)tid * (2.f/128.f), &s, &c);
                    twd[tid] = make_float2(c, s); }
    int s  = blockIdx.x >> 2;
    int w0 = (blockIdx.x & 3) << 5;
    const float2* sp = g_Bb + s * SLICE + w0;
    for (int idx = tid; idx < 4096; idx += 256) {
        int hh = idx >> 5, wl = idx & 31;
        t[idx] = sp[(hh << 7) + wl];
    }
    __syncthreads();
    #pragma unroll
    for (int hs = 6; hs >= 0; hs--) {
        int half = 1 << hs;
        for (int b = tid; b < 2048; b += 256) {
            int wl = b & 31, j = b >> 5;
            int grp = j >> hs, pos = j & (half - 1);
            int i0 = (((grp << (hs + 1)) + pos) << 5) + wl, i1 = i0 + (half << 5);
            float2 a = t[i0], c = t[i1];
            t[i0] = cadd(a, c);
            float2 d = csub(a, c);
            float2 wv = twd[pos << (6 - hs)];
            t[i1] = make_float2(d.x * wv.x + d.y * wv.y, d.y * wv.x - d.x * wv.y);
        }
        __syncthreads();
    }
    float2* dp = g_Fc + s * SLICE + w0;
    for (int idx = tid; idx < 4096; idx += 256) {
        int hh = idx >> 5, wl = idx & 31;
        dp[(hh << 7) + wl] = t[idx];
    }
}

// inverse cols with spectral divide fused at load:  g_Fc -> g_Bb
__global__ __launch_bounds__(256) void k_icols_div(float mu1, float mu2) {
    __shared__ float2 t[4096];
    __shared__ float2 twd[64];
    __shared__ float  d128[128];   // 2-2cos(2*pi*brev(pos)/128), indexed by POSITION
    int tid = threadIdx.x;
    if (tid < 64) { float s, c; sincospif((float)tid * (2.f/128.f), &s, &c);
                    twd[tid] = make_float2(c, s); }
    if (tid < 128) {
        int f = __brev((unsigned)tid) >> 25;
        d128[tid] = 2.f - 2.f * cospif((float)f * (2.f/128.f));
    }
    int s  = blockIdx.x >> 2;
    int k  = s & (NK - 1);
    int w0 = (blockIdx.x & 3) << 5;
    float dck = 2.f - 2.f * cospif((float)k * (2.f/31.f));
    __syncthreads();
    const float2* sp = g_Fc + s * SLICE + w0;
    for (int idx = tid; idx < 4096; idx += 256) {
        int hh = idx >> 5, wl = idx & 31;
        float2 v = sp[(hh << 7) + wl];
        float sc = 1.f / ((mu1 + mu2 * (dck + d128[hh] + d128[w0 + wl])) * 16384.f);
        t[idx] = make_float2(v.x * sc, v.y * sc);
    }
    __syncthreads();
    #pragma unroll
    for (int hs = 0; hs <= 6; hs++) {
        int half = 1 << hs;
        for (int b = tid; b < 2048; b += 256) {
            int wl = b & 31, j = b >> 5;
            int grp = j >> hs, pos = j & (half - 1);
            int i0 = (((grp << (hs + 1)) + pos) << 5) + wl, i1 = i0 + (half << 5);
            float2 wv = twd[pos << (6 - hs)];
            float2 x1 = t[i1];
            float2 tm = make_float2(x1.x * wv.x - x1.y * wv.y,
                                    x1.x * wv.y + x1.y * wv.x);
            float2 x0 = t[i0];
            t[i1] = csub(x0, tm);
            t[i0] = cadd(x0, tm);
        }
        __syncthreads();
    }
    float2* dp = g_Bb + s * SLICE + w0;
    for (int idx = tid; idx < 4096; idx += 256) {
        int hh = idx >> 5, wl = idx & 31;
        dp[(hh << 7) + wl] = t[idx];
    }
}

__global__ __launch_bounds__(256) void k_irows() {      // g_Bb -> g_Fc, w axis
    __shared__ float2 t[4096];
    __shared__ float2 twd[64];
    int tid = threadIdx.x;
    if (tid < 64) { float s, c; sincospif((float)tid * (2.f/128.f), &s, &c);
                    twd[tid] = make_float2(c, s); }
    int s  = blockIdx.x >> 2;
    int r0 = (blockIdx.x & 3) << 5;
    const float2* sp = g_Bb + s * SLICE + (r0 << 7);
    for (int idx = tid; idx < 4096; idx += 256) t[idx] = sp[idx];
    __syncthreads();
    #pragma unroll
    for (int hs = 0; hs <= 6; hs++) {
        int half = 1 << hs;
        for (int b = tid; b < 2048; b += 256) {
            int r = b >> 6, j = b & 63;
            int grp = j >> hs, pos = j & (half - 1);
            int i0 = (r << 7) + (grp << (hs + 1)) + pos, i1 = i0 + half;
            float2 wv = twd[pos << (6 - hs)];
            float2 x1 = t[i1];
            float2 tm = make_float2(x1.x * wv.x - x1.y * wv.y,
                                    x1.x * wv.y + x1.y * wv.x);
            float2 x0 = t[i0];
            t[i1] = csub(x0, tm);
            t[i0] = cadd(x0, tm);
        }
        __syncthreads();
    }
    float2* dp = g_Fc + s * SLICE + (r0 << 7);
    for (int idx = tid; idx < 4096; idx += 256) dp[idx] = t[idx];
}

// ---------------- fused: Hermitian C-synthesis + X/G1 update ----------------
// z_c = (H0 + 2*sum_{k=1..15} Re(Hk * e^{+2*pi*i*k*c/31})) / 31
__global__ __launch_bounds__(256) void k_cinv(const float* __restrict__ Y,
                                              const float* __restrict__ inW,
                                              float mu1, float* __restrict__ out)
{
    __shared__ float2 tw[NC];  // (cos, -sin)(2*pi*m/31)
    int tid = threadIdx.x;
    if (tid < NC) { float s, c; sincospif((float)tid * (2.f/31.f), &s, &c);
                    tw[tid] = make_float2(c, -s); }
    __syncthreads();

    int p = blockIdx.x * 256 + tid;
    int n = p >> 14, hw = p & 16383;
    int fb = (n * NK) * SLICE + hw;

    float2 H[NK];
    #pragma unroll
    for (int k = 0; k < NK; k++) {
        float2 v = g_Fc[fb + k * SLICE];
        H[k] = (k == 0) ? make_float2(v.x, 0.f) : make_float2(2.f * v.x, 2.f * v.y);
    }

    int base = n * (NC * SLICE) + hw;
    const float inv31 = 1.f / 31.f;
    for (int c = 0; c < NC; c++) {
        float acc = H[0].x;
        int m = 0;
        #pragma unroll
        for (int k = 1; k < NK; k++) {
            m += c; if (m >= NC) m -= NC;
            float2 t = tw[m];
            // Re(Hk * e^{+i theta}) = Hx*cos - Hy*sin = Hx*t.x + Hy*t.y
            acc = fmaf(H[k].x, t.x, acc);
            acc = fmaf(H[k].y, t.y, acc);
        }
        float z = acc * inv31;
        int i = base + c * SLICE;
        if (out != nullptr) {
            out[i] = z;
        } else {
            g_Z[i] = z;
            float xw = inW[i], y = Y[i], g1 = g_G1[i];
            float x = (xw * y + mu1 * z - g1) / (xw + mu1);
            g_G1[i] = fmaf(mu1, x - z, g1);
            g_X[i]  = x;
        }
    }
}

// ---------------- launch ----------------------------------------------------
extern "C" void kernel_launch(void* const* d_in, const int* in_sizes, int n_in,
                              void* d_out, int out_size) {
    const float* Y   = (const float*)d_in[0];
    const float* inW = (const float*)d_in[1];
    float* out = (float*)d_out;

    k_init<<<(VOL + 255) / 256, 256>>>(Y);

    double mu1d = 0.1, mu2d = 0.1, mu2pd = 0.0;
    const double lam = 0.1;
    const int PB = PEN / 256;        // 256 blocks for pencil kernels
    const int FB = NB * NK * 4;      // 256 blocks for FFT pass kernels

    for (int it = 0; it < 20; it++) {
        float mu1 = (float)mu1d, mu2 = (float)mu2d, mu2p = (float)mu2pd;
        float inv_mu2 = (float)(1.0 / mu2d);
        float thr = (float)(lam / mu2d);
        int pp = it & 1;

        k_cfwd<<<PB, 256>>>(pp, mu1, mu2, mu2p, inv_mu2, thr);
        k_rows_fwd<<<FB, 256>>>();
        k_cols_fwd<<<FB, 256>>>();
        k_icols_div<<<FB, 256>>>(mu1, mu2);
        k_irows<<<FB, 256>>>();
        k_cinv<<<PB, 256>>>(Y, inW, mu1, (it == 19) ? out : nullptr);

        mu2pd = mu2d;
        mu1d *= 1.05;
        mu2d *= 1.05;
    }
}

// round 3
// speedup vs baseline: 1.9268x; 1.4592x over previous
#include <cuda_runtime.h>
#include <math.h>

#define NB 4
#define NC 31
#define NK 16                 // Hermitian half of C-spectrum
#define SLICE 16384           // 128*128
#define VOL   (NB*NC*SLICE)   // 2031616
#define PEN   (NB*SLICE)      // 65536 pencils

// ---------------- static scratch --------------------------------------------
__device__ float  g_Z[VOL];
__device__ float  g_X[VOL];
__device__ float  g_G1[VOL];
__device__ float  g_Ph[2][VOL];
__device__ float  g_Pv[2][VOL];
__device__ float  g_Ps[VOL];
__device__ float2 g_S[NB*NK*SLICE];   // spectral working buffer

// ---------------- helpers ---------------------------------------------------
__device__ __forceinline__ float shrinkf(float x, float t) {
    return copysignf(fmaxf(fabsf(x) - t, 0.0f), x);
}
__device__ __forceinline__ float2 cadd(float2 a, float2 b){ return make_float2(a.x+b.x, a.y+b.y); }
__device__ __forceinline__ float2 csub(float2 a, float2 b){ return make_float2(a.x-b.x, a.y-b.y); }
// d * (wx - i*wy)
__device__ __forceinline__ float2 cmuln(float2 d, float2 w){
    return make_float2(d.x*w.x + d.y*w.y, d.y*w.x - d.x*w.y);
}
// d * (wx + i*wy)
__device__ __forceinline__ float2 cmulp(float2 d, float2 w){
    return make_float2(d.x*w.x - d.y*w.y, d.x*w.y + d.y*w.x);
}
__device__ __forceinline__ float2 shfl2(float2 v, int m){
    float2 r;
    r.x = __shfl_xor_sync(0xffffffffu, v.x, m);
    r.y = __shfl_xor_sync(0xffffffffu, v.y, m);
    return r;
}

// ---------------- warp-level 128-pt FFT (4 complex per lane) -----------------
// element e = j*32 + t. twd[m] = (cospi(m/64), sinpi(m/64)) = exp(+2*pi*i*m/128) parts.
// fwd = DIF sign -, natural -> bit-reversed position. inv = DIT sign +, bitrev -> natural.
__device__ __forceinline__ void wfft_fwd(float2 v[4], const float2* __restrict__ twd, int t){
    {   // hs=6, half=64: local pairs (0,2),(1,3), pos = (j&1)*32 + t
        float2 w0 = twd[t], w1 = twd[32 + t];
        float2 a = v[0], b = v[2]; v[0] = cadd(a,b); v[2] = cmuln(csub(a,b), w0);
        a = v[1]; b = v[3]; v[1] = cadd(a,b); v[3] = cmuln(csub(a,b), w1);
    }
    {   // hs=5, half=32: local pairs (0,1),(2,3), pos = t
        float2 w = twd[2*t];
        float2 a = v[0], b = v[1]; v[0] = cadd(a,b); v[1] = cmuln(csub(a,b), w);
        a = v[2]; b = v[3]; v[2] = cadd(a,b); v[3] = cmuln(csub(a,b), w);
    }
    #pragma unroll
    for (int hs = 4; hs >= 0; hs--){   // shuffle stages, half = 16..1
        int half = 1 << hs;
        float2 w = twd[(t & (half-1)) << (6 - hs)];
        bool up = (t & half) != 0;
        #pragma unroll
        for (int j = 0; j < 4; j++){
            float2 pv = shfl2(v[j], half);
            v[j] = up ? cmuln(csub(pv, v[j]), w) : cadd(v[j], pv);
        }
    }
}

__device__ __forceinline__ void wfft_inv(float2 v[4], const float2* __restrict__ twd, int t){
    #pragma unroll
    for (int hs = 0; hs <= 4; hs++){   // shuffle stages, half = 1..16
        int half = 1 << hs;
        float2 w = twd[(t & (half-1)) << (6 - hs)];
        bool up = (t & half) != 0;
        #pragma unroll
        for (int j = 0; j < 4; j++){
            float2 u = up ? cmulp(v[j], w) : v[j];
            float2 pu = shfl2(u, half);
            v[j] = up ? csub(pu, u) : cadd(u, pu);
        }
    }
    {   // hs=5, half=32
        float2 w = twd[2*t];
        float2 tm = cmulp(v[1], w); float2 x0 = v[0]; v[0] = cadd(x0,tm); v[1] = csub(x0,tm);
        tm = cmulp(v[3], w); x0 = v[2]; v[2] = cadd(x0,tm); v[3] = csub(x0,tm);
    }
    {   // hs=6, half=64
        float2 w0 = twd[t], w1 = twd[32 + t];
        float2 tm = cmulp(v[2], w0); float2 x0 = v[0]; v[0] = cadd(x0,tm); v[2] = csub(x0,tm);
        tm = cmulp(v[3], w1); x0 = v[1]; v[1] = cadd(x0,tm); v[3] = csub(x0,tm);
    }
}

// ---------------- init ------------------------------------------------------
__global__ void k_init(const float* __restrict__ Y) {
    int i = blockIdx.x * blockDim.x + threadIdx.x;
    if (i >= VOL) return;
    float y = Y[i];
    g_Z[i] = y; g_X[i] = y;
    g_G1[i] = 0.f;
    g_Ph[0][i] = 0.f; g_Pv[0][i] = 0.f; g_Ps[i] = 0.f;
}

// ---------------- fused: pencil phase + real C-DFT + forward row FFT --------
__global__ __launch_bounds__(256) void k_cfwd_rows(int pp, float mu1, float mu2,
                                                   float mu2p, float inv_mu2, float thr)
{
    __shared__ float2 tw31[NC];
    __shared__ float2 twd[64];
    __shared__ float2 sF[NK*256];
    int tid = threadIdx.x;
    if (tid < NC){ float s, c; sincospif((float)tid*(2.f/31.f), &s, &c); tw31[tid] = make_float2(c, -s); }
    if (tid < 64){ float s, c; sincospif((float)tid*(1.f/64.f), &s, &c); twd[tid]  = make_float2(c, s); }
    __syncthreads();

    int p  = blockIdx.x * 256 + tid;
    int hw = p & 16383;
    int h  = hw >> 7, w = hw & 127;
    int ow1 = ((w + 1)   & 127) - w;
    int owm = ((w + 127) & 127) - w;
    int oh1 = ((((h + 1)   & 127) - h) << 7);
    int ohm = ((((h + 127) & 127) - h) << 7);
    int base = (p >> 14) * (NC * SLICE) + hw;

    const float* __restrict__ Ph_in  = g_Ph[pp];
    float*       __restrict__ Ph_out = g_Ph[pp ^ 1];
    const float* __restrict__ Pv_in  = g_Pv[pp];
    float*       __restrict__ Pv_out = g_Pv[pp ^ 1];

    float z0  = g_Z[base];
    float z30 = g_Z[base + 30 * SLICE];
    float As_prev;
    {
        float d  = z30 - z0;
        float g2 = g_Ps[base + 30 * SLICE] - mu2p * d;
        float q  = g2 * inv_mu2;
        As_prev  = shrinkf(d - q, thr) + q;
    }

    float2 F[NK];
    #pragma unroll
    for (int k = 0; k < NK; k++) F[k] = make_float2(0.f, 0.f);

    float zc = z0;
    for (int c = 0; c < NC; c++) {
        int i = base + c * SLICE;
        float znext = (c < 30) ? g_Z[i + SLICE] : z0;
        float zw1 = g_Z[i + ow1], zwm = g_Z[i + owm];
        float zh1 = g_Z[i + oh1], zhm = g_Z[i + ohm];

        float dh  = zc - zw1;
        float g2h = Ph_in[i] - mu2p * dh;
        float qh  = g2h * inv_mu2;
        float Ah  = shrinkf(dh - qh, thr) + qh;
        Ph_out[i] = mu2 * Ah;
        float dhm  = zwm - zc;
        float g2hm = Ph_in[i + owm] - mu2p * dhm;
        float qhm  = g2hm * inv_mu2;
        float Ahm  = shrinkf(dhm - qhm, thr) + qhm;

        float dv  = zc - zh1;
        float g2v = Pv_in[i] - mu2p * dv;
        float qv  = g2v * inv_mu2;
        float Av  = shrinkf(dv - qv, thr) + qv;
        Pv_out[i] = mu2 * Av;
        float dvm  = zhm - zc;
        float g2vm = Pv_in[i + ohm] - mu2p * dvm;
        float qvm  = g2vm * inv_mu2;
        float Avm  = shrinkf(dvm - qvm, thr) + qvm;

        float ds  = zc - znext;
        float g2s = g_Ps[i] - mu2p * ds;
        float qs  = g2s * inv_mu2;
        float As  = shrinkf(ds - qs, thr) + qs;
        g_Ps[i]   = mu2 * As;

        float numer = mu1 * g_X[i] + g_G1[i]
                    + mu2 * ((Ah - Ahm) + (Av - Avm) + (As - As_prev));
        As_prev = As;

        F[0].x += numer;
        int m = 0;
        #pragma unroll
        for (int k = 1; k < NK; k++) {
            m += c; if (m >= NC) m -= NC;
            float2 t = tw31[m];
            F[k].x = fmaf(numer, t.x, F[k].x);
            F[k].y = fmaf(numer, t.y, F[k].y);
        }
        zc = znext;
    }

    #pragma unroll
    for (int k = 0; k < NK; k++) sF[k*256 + tid] = F[k];
    __syncthreads();

    // forward row FFT: 32 tasks (16 k x 2 rows), 8 warps
    int wid = tid >> 5, t = tid & 31;
    int n_b = blockIdx.x >> 6;
    int h0  = (blockIdx.x & 63) << 1;
    #pragma unroll
    for (int task = wid; task < 32; task += 8){
        int k = task >> 1, r = task & 1;
        float2 v[4];
        #pragma unroll
        for (int j = 0; j < 4; j++) v[j] = sF[k*256 + r*128 + t + 32*j];
        wfft_fwd(v, twd, t);
        float2* dst = g_S + (size_t)(n_b*NK + k)*SLICE + (h0 + r)*128;
        #pragma unroll
        for (int j = 0; j < 4; j++) dst[t + 32*j] = v[j];
    }
}

// ---------------- fused: col fwd FFT + spectral divide + col inv FFT --------
__global__ __launch_bounds__(256) void k_ccols(float mu1, float mu2){
    __shared__ float2 twd[64];
    __shared__ float  d128s[128];   // 2-2cos(2*pi*brev(pos)/128), by POSITION
    __shared__ float2 sT[16*129];
    int tid = threadIdx.x;
    if (tid < 64){ float s, c; sincospif((float)tid*(1.f/64.f), &s, &c); twd[tid] = make_float2(c, s); }
    if (tid < 128){
        int f = __brev((unsigned)tid) >> 25;
        d128s[tid] = 2.f - 2.f * cospif((float)f * (1.f/64.f));
    }

    int s  = blockIdx.x >> 3;
    int w0 = (blockIdx.x & 7) << 4;
    int kc = s & (NK - 1);
    float dck = 2.f - 2.f * cospif((float)kc * (2.f/31.f));

    const float2* src = g_S + (size_t)s * SLICE + w0;
    for (int idx = tid; idx < 2048; idx += 256){
        int h = idx >> 4, wl = idx & 15;
        sT[wl*129 + h] = src[h*128 + wl];
    }
    __syncthreads();

    int wid = tid >> 5, t = tid & 31;
    #pragma unroll
    for (int ci = 0; ci < 2; ci++){
        int wl = wid*2 + ci;
        float2 v[4];
        #pragma unroll
        for (int j = 0; j < 4; j++) v[j] = sT[wl*129 + t + 32*j];
        wfft_fwd(v, twd, t);
        float dw = d128s[w0 + wl];
        #pragma unroll
        for (int j = 0; j < 4; j++){
            float sc = 1.f / ((mu1 + mu2 * (dck + d128s[t + 32*j] + dw)) * 16384.f);
            v[j].x *= sc; v[j].y *= sc;
        }
        wfft_inv(v, twd, t);
        #pragma unroll
        for (int j = 0; j < 4; j++) sT[wl*129 + t + 32*j] = v[j];
    }
    __syncthreads();

    float2* dst = g_S + (size_t)s * SLICE + w0;
    for (int idx = tid; idx < 2048; idx += 256){
        int h = idx >> 4, wl = idx & 15;
        dst[h*128 + wl] = sT[wl*129 + h];
    }
}

// ---------------- fused: inverse row FFT + Hermitian C-synthesis + update ---
__global__ __launch_bounds__(512) void k_irows_cinv(const float* __restrict__ Y,
                                                    const float* __restrict__ inW,
                                                    float mu1, float* __restrict__ out)
{
    __shared__ float2 twd[64];
    __shared__ float2 tw31[NC];
    __shared__ float2 sH[NK*128];
    int tid = threadIdx.x;
    if (tid < 64){ float s, c; sincospif((float)tid*(1.f/64.f), &s, &c); twd[tid] = make_float2(c, s); }
    if (tid >= 64 && tid < 64 + NC){
        int m = tid - 64;
        float s, c; sincospif((float)m*(2.f/31.f), &s, &c);
        tw31[m] = make_float2(c, -s);
    }
    __syncthreads();

    int n = blockIdx.x >> 7, h = blockIdx.x & 127;
    int wid = tid >> 5, t = tid & 31;
    {
        int k = wid;   // 16 warps <-> 16 k
        const float2* src = g_S + (size_t)(n*NK + k)*SLICE + h*128;
        float2 v[4];
        #pragma unroll
        for (int j = 0; j < 4; j++) v[j] = src[t + 32*j];
        wfft_inv(v, twd, t);
        #pragma unroll
        for (int j = 0; j < 4; j++) sH[k*128 + t + 32*j] = v[j];
    }
    __syncthreads();

    int w = tid & 127, cg = tid >> 7;   // 4 c-groups per pencil
    float Hx[NK], Hy[NK];
    const float i31 = 1.f/31.f, i31x2 = 2.f/31.f;
    Hx[0] = sH[w].x * i31;
    #pragma unroll
    for (int k = 1; k < NK; k++){
        float2 v = sH[k*128 + w];
        Hx[k] = v.x * i31x2; Hy[k] = v.y * i31x2;
    }

    int c0 = cg * 8, c1 = (cg == 3) ? 31 : c0 + 8;
    int base = n * (NC * SLICE) + h*128 + w;
    for (int c = c0; c < c1; c++){
        float acc = Hx[0];
        int m = 0;
        #pragma unroll
        for (int k = 1; k < NK; k++){
            m += c; if (m >= NC) m -= NC;
            float2 tt = tw31[m];
            acc = fmaf(Hx[k], tt.x, acc);
            acc = fmaf(Hy[k], tt.y, acc);
        }
        int i = base + c * SLICE;
        if (out != nullptr) {
            out[i] = acc;
        } else {
            g_Z[i] = acc;
            float xw = inW[i], y = Y[i], g1 = g_G1[i];
            float x = (xw * y + mu1 * acc - g1) / (xw + mu1);
            g_G1[i] = fmaf(mu1, x - acc, g1);
            g_X[i]  = x;
        }
    }
}

// ---------------- launch ----------------------------------------------------
extern "C" void kernel_launch(void* const* d_in, const int* in_sizes, int n_in,
                              void* d_out, int out_size) {
    const float* Y   = (const float*)d_in[0];
    const float* inW = (const float*)d_in[1];
    float* out = (float*)d_out;

    k_init<<<(VOL + 255) / 256, 256>>>(Y);

    double mu1d = 0.1, mu2d = 0.1, mu2pd = 0.0;
    const double lam = 0.1;

    for (int it = 0; it < 20; it++) {
        float mu1 = (float)mu1d, mu2 = (float)mu2d, mu2p = (float)mu2pd;
        float inv_mu2 = (float)(1.0 / mu2d);
        float thr = (float)(lam / mu2d);
        int pp = it & 1;

        k_cfwd_rows<<<PEN/256, 256>>>(pp, mu1, mu2, mu2p, inv_mu2, thr);
        k_ccols<<<NB*NK*8, 256>>>(mu1, mu2);
        k_irows_cinv<<<NB*128, 512>>>(Y, inW, mu1, (it == 19) ? out : nullptr);

        mu2pd = mu2d;
        mu1d *= 1.05;
        mu2d *= 1.05;
    }
}